// round 4
// baseline (speedup 1.0000x reference)
#include <cuda_runtime.h>
#include <cstdint>

// CenterLoss: mean_i ||x[i] - centers[labels[i]]||^2
// B=16384, C=4000, D=512
// Inputs: x [B*D] f32, labels [B] int32, centers [C*D] f32. Output: scalar f32.

#define B_ROWS 16384
#define C_ROWS 4000
#define D_VEC  128               // 512 floats = 128 float4 per row
#define WARPS_PER_BLOCK 8
#define THREADS (WARPS_PER_BLOCK * 32)
#define ROWS_PER_WARP 2          // both rows' loads fully front-batched (16 LDG.128)
#define GRID_BLOCKS (B_ROWS / (WARPS_PER_BLOCK * ROWS_PER_WARP))  // 1024

__global__ __launch_bounds__(THREADS)
void center_loss_kernel(const float4* __restrict__ x,
                        const int* __restrict__ labels,
                        const float4* __restrict__ centers,
                        float* __restrict__ out)
{
    const int warp = threadIdx.x >> 5;
    const int lane = threadIdx.x & 31;
    const int row0 = (blockIdx.x * WARPS_PER_BLOCK + warp) * ROWS_PER_WARP;

    // Resolve both center addresses first (address dependency off the critical path)
    int lab0 = labels[row0];
    int lab1 = labels[row0 + 1];
    lab0 = min(max(lab0, 0), C_ROWS - 1);
    lab1 = min(max(lab1, 0), C_ROWS - 1);

    const float4* xr0 = x       + (size_t)row0 * D_VEC;
    const float4* xr1 = xr0     + D_VEC;
    const float4* cr0 = centers + (size_t)lab0 * D_VEC;
    const float4* cr1 = centers + (size_t)lab1 * D_VEC;

    // Front-batch ALL 16 LDG.128 (8 KB in flight per warp) before any compute.
    // x is a one-shot stream -> evict-first (__ldcs) so it never displaces
    // the L2-resident centers working set.
    float4 a0[4], a1[4], b0[4], b1[4];
    #pragma unroll
    for (int i = 0; i < 4; i++) a0[i] = __ldcs(xr0 + lane + 32 * i);
    #pragma unroll
    for (int i = 0; i < 4; i++) a1[i] = __ldcs(xr1 + lane + 32 * i);
    #pragma unroll
    for (int i = 0; i < 4; i++) b0[i] = __ldg(cr0 + lane + 32 * i);
    #pragma unroll
    for (int i = 0; i < 4; i++) b1[i] = __ldg(cr1 + lane + 32 * i);

    float s = 0.0f;
    #pragma unroll
    for (int i = 0; i < 4; i++) {
        float dx, dy, dz, dw;
        dx = a0[i].x - b0[i].x; dy = a0[i].y - b0[i].y;
        dz = a0[i].z - b0[i].z; dw = a0[i].w - b0[i].w;
        s += dx*dx + dy*dy + dz*dz + dw*dw;
        dx = a1[i].x - b1[i].x; dy = a1[i].y - b1[i].y;
        dz = a1[i].z - b1[i].z; dw = a1[i].w - b1[i].w;
        s += dx*dx + dy*dy + dz*dz + dw*dw;
    }

    // warp reduce
    #pragma unroll
    for (int o = 16; o > 0; o >>= 1)
        s += __shfl_xor_sync(0xFFFFFFFFu, s, o);

    __shared__ float warp_sums[WARPS_PER_BLOCK];
    if (lane == 0) warp_sums[warp] = s;
    __syncthreads();

    if (warp == 0) {
        float v = (lane < WARPS_PER_BLOCK) ? warp_sums[lane] : 0.0f;
        #pragma unroll
        for (int o = 4; o > 0; o >>= 1)
            v += __shfl_xor_sync(0xFFFFFFFFu, v, o);
        if (lane == 0)
            atomicAdd(out, v * (1.0f / (float)B_ROWS));
    }
}

extern "C" void kernel_launch(void* const* d_in, const int* in_sizes, int n_in,
                              void* d_out, int out_size)
{
    const float4* x       = (const float4*)d_in[0];
    const int*    labels  = (const int*)d_in[1];
    const float4* centers = (const float4*)d_in[2];
    float*        out     = (float*)d_out;

    cudaMemsetAsync(out, 0, sizeof(float));
    center_loss_kernel<<<GRID_BLOCKS, THREADS>>>(x, labels, centers, out);
}